// round 17
// baseline (speedup 1.0000x reference)
#include <cuda_runtime.h>
#include <math.h>

// Problem constants
#define Bq 2
#define Sq 2048
#define DM 1024
#define Hq 16
#define DHq 64

// ---------------------------------------------------------------------------
// Scratch (__device__ globals)
// tf32 BIT PATTERNS; K/D perm within 8-groups: k -> ((k&3)<<1)|(k>>2)
// qh carries the 1/8 score scale. vh transposed per 128-tile: [z][kt][d][128],
// natural row order (PV uses the delta=perm8 k-relabeling).
// ---------------------------------------------------------------------------
__device__ unsigned g_qh [(size_t)Bq * Hq * Sq * DHq];   // tf32, d-perm, x0.125
__device__ unsigned g_kh [(size_t)Bq * Hq * Sq * DHq];   // tf32, d-perm
__device__ unsigned g_vh [(size_t)Bq * Hq * Sq * DHq];   // [z][16][64][128] tf32
__device__ unsigned g_ctx[(size_t)Bq * Sq * DM];          // tf32, d-perm
__device__ float    g_linv[(size_t)Bq * Hq * Sq];         // per-row 1/l
__device__ unsigned g_wq[(size_t)DM * DM];                // weights tf32, k-perm
__device__ unsigned g_wk[(size_t)DM * DM];
__device__ unsigned g_wv[(size_t)DM * DM];
__device__ unsigned g_wo[(size_t)DM * DM];

// ---------------------------------------------------------------------------
// Helpers
// ---------------------------------------------------------------------------
__device__ __forceinline__ unsigned f2tf32(float f) {
    unsigned r; asm("cvt.rna.tf32.f32 %0, %1;" : "=r"(r) : "f"(f)); return r;
}
__device__ __forceinline__ int perm8(int r) { return ((r & 3) << 1) | (r >> 2); }
__device__ __forceinline__ void cpa16(void* dst, const void* src) {
    unsigned d = (unsigned)__cvta_generic_to_shared(dst);
    asm volatile("cp.async.cg.shared.global [%0], [%1], 16;" :: "r"(d), "l"(src));
}
__device__ __forceinline__ void cp_commit() { asm volatile("cp.async.commit_group;"); }
__device__ __forceinline__ void cp_wait1()  { asm volatile("cp.async.wait_group 1;"); }
__device__ __forceinline__ void cp_wait0()  { asm volatile("cp.async.wait_group 0;"); }

__device__ __forceinline__ void mma8(float* c, unsigned a0, unsigned a1, unsigned a2,
                                     unsigned a3, unsigned b0, unsigned b1) {
    asm volatile(
        "mma.sync.aligned.m16n8k8.row.col.f32.tf32.tf32.f32 "
        "{%0,%1,%2,%3}, {%4,%5,%6,%7}, {%8,%9}, {%0,%1,%2,%3};"
        : "+f"(c[0]), "+f"(c[1]), "+f"(c[2]), "+f"(c[3])
        : "r"(a0), "r"(a1), "r"(a2), "r"(a3), "r"(b0), "r"(b1));
}

// ---------------------------------------------------------------------------
// Prep: WEIGHTS ONLY -> tf32 bits, K-dim permuted within 8-groups.
// ---------------------------------------------------------------------------
struct PrepP { const float* in[4]; unsigned* out[4]; };

__global__ __launch_bounds__(256)
void prep_cvt(PrepP pp)
{
    int z = blockIdx.y;
    int idx4 = (blockIdx.x * 256 + threadIdx.x) * 4;
    const float* in = pp.in[z];
    unsigned* out = pp.out[z];
    float4 v = *(const float4*)&in[idx4];
    int base = idx4 & ~7;
    int off  = (idx4 & 7) ? 1 : 0;
    out[base + off + 0] = f2tf32(v.x);
    out[base + off + 2] = f2tf32(v.y);
    out[base + off + 4] = f2tf32(v.z);
    out[base + off + 6] = f2tf32(v.w);
}

// ---------------------------------------------------------------------------
// QKV GEMM (A raw fp32 + cvt; W tf32 k-perm paired). Head-layout epilogues:
// nperm 1 = d-perm scatter (q/k); 2 = transposed V tile, natural rows.
// ---------------------------------------------------------------------------
struct GemmP {
    const unsigned *X, *X1, *X2;
    const unsigned *W, *W1, *W2;
    const float *b0_, *b1_, *b2_;
    void *Y, *Y1, *Y2;
    int K;
    float ps[3];
    int nperm[3];
};

#define BUF_WORDS 5120     // 128*40
#define G_SMEM_BYTES (4 * BUF_WORDS * 4)

__global__ __launch_bounds__(256, 2)
void gemm_qkv(GemmP p)
{
    constexpr int ASA = 36;
    constexpr int ASB = 40;

    const int m0 = blockIdx.y * 128;
    const int n0 = blockIdx.x * 128;
    const int z  = blockIdx.z;
    const int tid = threadIdx.x, lane = tid & 31, warp = tid >> 5;
    const int wm = warp & 1, wn = warp >> 1;

    const unsigned *X = p.X, *W = p.W; const float* bias = p.b0_; void* Y = p.Y;
    float pscale = p.ps[0]; int nperm = p.nperm[0];
    if (z == 1) { X = p.X1; W = p.W1; bias = p.b1_; Y = p.Y1; pscale = p.ps[1]; nperm = p.nperm[1]; }
    else if (z == 2) { X = p.X2; W = p.W2; bias = p.b2_; Y = p.Y2; pscale = p.ps[2]; nperm = p.nperm[2]; }

    extern __shared__ unsigned smu[];
    unsigned* Abuf[2] = { smu,                 smu + BUF_WORDS     };
    unsigned* Bbuf[2] = { smu + 2 * BUF_WORDS, smu + 3 * BUF_WORDS };

    auto loadA = [&](unsigned* As_, int k0) {
        int r0 = tid >> 3, c = (tid & 7) * 4;
#pragma unroll
        for (int it = 0; it < 4; it++) {
            int r = r0 + it * 32;
            cpa16(&As_[r * ASA + c], &X[(long long)(m0 + r) * p.K + k0 + c]);
        }
    };
    auto loadB = [&](unsigned* Bs_, int k0) {
        int r0 = tid >> 3, c = (tid & 7) * 4;
#pragma unroll
        for (int it = 0; it < 4; it++) {
            int r = r0 + it * 32;
            cpa16(&Bs_[r * ASB + c], &W[(long long)(n0 + r) * p.K + k0 + c]);
        }
    };

    float acc[4][4][4] = {};

    loadA(Abuf[0], 0); loadB(Bbuf[0], 0); cp_commit();
    int st = 0;
    for (int k0 = 0; k0 < p.K; k0 += 32) {
        if (k0 + 32 < p.K) { loadA(Abuf[st ^ 1], k0 + 32); loadB(Bbuf[st ^ 1], k0 + 32); }
        cp_commit();
        cp_wait1();
        __syncthreads();

        const unsigned* As_ = Abuf[st];
        const unsigned* Bs_ = Bbuf[st];
        const float* Af = (const float*)As_;
#pragma unroll
        for (int kk = 0; kk < 32; kk += 8) {
            const int kc = kk + (lane & 3);
            const int kp = kk + 2 * (lane & 3);
            unsigned a[4][4];
#pragma unroll
            for (int i = 0; i < 4; i++) {
                int mr = wm * 64 + i * 16 + (lane >> 2);
                a[i][0] = f2tf32(Af[mr * ASA + kc]);
                a[i][1] = f2tf32(Af[(mr + 8) * ASA + kc]);
                a[i][2] = f2tf32(Af[mr * ASA + kc + 4]);
                a[i][3] = f2tf32(Af[(mr + 8) * ASA + kc + 4]);
            }
            unsigned b[4][2];
#pragma unroll
            for (int j = 0; j < 4; j++) {
                int nr = wn * 32 + j * 8 + (lane >> 2);
                uint2 bb = *(const uint2*)&Bs_[nr * ASB + kp];
                b[j][0] = bb.x; b[j][1] = bb.y;
            }
#pragma unroll
            for (int i = 0; i < 4; i++)
#pragma unroll
                for (int j = 0; j < 4; j++)
                    mma8(acc[i][j], a[i][0], a[i][1], a[i][2], a[i][3], b[j][0], b[j][1]);
        }
        __syncthreads();
        st ^= 1;
    }

#pragma unroll
    for (int i = 0; i < 4; i++)
#pragma unroll
        for (int j = 0; j < 4; j++)
#pragma unroll
            for (int h = 0; h < 2; h++) {
                int m = m0 + wm * 64 + i * 16 + (lane >> 2) + h * 8;
                int n = n0 + wn * 32 + j * 8 + (lane & 3) * 2;
                float v0 = acc[i][j][h * 2]     + bias[n];
                float v1 = acc[i][j][h * 2 + 1] + bias[n + 1];
                int b_ = m >> 11;
                int s  = m & (Sq - 1);
                int hh = n >> 6;
                int d  = n & (DHq - 1);
                unsigned u0 = f2tf32(v0 * pscale);
                unsigned u1 = f2tf32(v1 * pscale);
                unsigned* Yu = (unsigned*)Y;
                int zz = b_ * Hq + hh;
                if (nperm == 2) {
                    long long a0 = (((long long)zz * 16 + (s >> 7)) * 64 + d) * 128 + (s & 127);
                    Yu[a0]       = u0;
                    Yu[a0 + 128] = u1;
                } else {
                    long long rowb = ((long long)zz * Sq + s) * DHq;
                    int r0 = d & 7;
                    Yu[rowb + (d & ~7) + perm8(r0)]     = u0;
                    Yu[rowb + (d & ~7) + perm8(r0 + 1)] = u1;
                }
            }
}

// ---------------------------------------------------------------------------
// Flash pass A only: ctx + row inverse sums.
// 256 threads, 8 warps x 16 rows, 2 CTAs/SM, pipelined K/V prefetch,
// shuffle-free PV via delta=perm8 k-relabeling.
// ---------------------------------------------------------------------------
#define QST 72
#define KST 72
#define VST 136
#define FK_OFF 9216
#define FV_OFF 18432
#define F_SMEM_BYTES (27136 * 4)

__global__ __launch_bounds__(256, 2)
void attn_flash_a(const unsigned* __restrict__ qh, const unsigned* __restrict__ kh,
                  const unsigned* __restrict__ vhT, unsigned* __restrict__ ctx,
                  float* __restrict__ linv)
{
    const int qt = (int)gridDim.x - 1 - (int)blockIdx.x;
    const int z  = blockIdx.y;
    const int tid = threadIdx.x, lane = tid & 31, warp = tid >> 5;

    extern __shared__ unsigned smu[];
    unsigned* Qs = smu;
    unsigned* Ks = smu + FK_OFF;
    unsigned* Vs = smu + FV_OFF;

    const unsigned* Qg  = qh  + ((long long)z * Sq + qt * 128) * DHq;
    const unsigned* Kg  = kh  + (long long)z * Sq * DHq;
    const unsigned* VgT = vhT + (long long)z * Sq * DHq;

    for (int i = tid; i < 128 * 16; i += 256) {
        int r = i >> 4, c4 = (i & 15) * 4;
        *(uint4*)&Qs[r * QST + c4] = *(const uint4*)&Qg[r * 64 + c4];
    }

    auto loadK = [&](int kt) {
        for (int i = tid; i < 128 * 16; i += 256) {
            int r = i >> 4, c4 = (i & 15) * 4;
            cpa16(&Ks[r * KST + c4], &Kg[((long long)kt * 128 + r) * 64 + c4]);
        }
    };
    auto loadV = [&](int kt) {
        for (int i = tid; i < 64 * 32; i += 256) {
            int d = i >> 5, c4 = (i & 31) * 4;
            cpa16(&Vs[d * VST + c4], &VgT[(long long)kt * 8192 + d * 128 + c4]);
        }
    };

    const unsigned* Qw = &Qs[(warp * 16) * QST];
    const int rq = lane >> 2;
    const int q4 = lane & 3;
    const int rbase = qt * 128 + warp * 16 + rq;

    float cacc[8][4] = {};
    float l0 = 0.f, l1 = 0.f;
    float p[8][4];

    loadK(0); cp_commit();
    loadV(0); cp_commit();

    for (int kt = 0; kt <= qt; kt++) {
        cp_wait1();
        __syncthreads();

        bool diag = (kt == qt);

        // S half 0 (overlaps V load)
#pragma unroll
        for (int j = 0; j < 8; j++) { p[j][0] = p[j][1] = p[j][2] = p[j][3] = 0.f; }
#pragma unroll
        for (int ks = 0; ks < 8; ks++) {
            const int kp = ks * 8 + 2 * q4;
            uint2 qlo = *(const uint2*)&Qw[rq * QST + kp];
            uint2 qhi = *(const uint2*)&Qw[(rq + 8) * QST + kp];
#pragma unroll
            for (int j = 0; j < 8; j++) {
                int n = j * 8 + rq;
                uint2 kb = *(const uint2*)&Ks[n * KST + kp];
                mma8(p[j], qlo.x, qhi.x, qlo.y, qhi.y, kb.x, kb.y);
            }
        }
#pragma unroll
        for (int j = 0; j < 8; j++) {
            int c0 = kt * 128 + j * 8 + 2 * q4;
            float e0 = (!diag || c0     <= rbase    ) ? __expf(p[j][0]) : 0.f;
            float e1 = (!diag || c0 + 1 <= rbase    ) ? __expf(p[j][1]) : 0.f;
            float e2 = (!diag || c0     <= rbase + 8) ? __expf(p[j][2]) : 0.f;
            float e3 = (!diag || c0 + 1 <= rbase + 8) ? __expf(p[j][3]) : 0.f;
            p[j][0] = e0; p[j][1] = e1; p[j][2] = e2; p[j][3] = e3;
            l0 += e0 + e1; l1 += e2 + e3;
        }

        cp_wait0();
        __syncthreads();

        // PV half 0 (A-frags straight from p registers)
#pragma unroll
        for (int t = 0; t < 8; t++) {
            unsigned a0 = f2tf32(p[t][0]);
            unsigned a1 = f2tf32(p[t][2]);
            unsigned a2 = f2tf32(p[t][1]);
            unsigned a3 = f2tf32(p[t][3]);
            int krp = t * 8 + 2 * q4;
#pragma unroll
            for (int j = 0; j < 8; j++) {
                int n = j * 8 + rq;
                uint2 vb = *(const uint2*)&Vs[n * VST + krp];
                mma8(cacc[j], a0, a1, a2, a3, vb.x, vb.y);
            }
        }

        // S half 1
#pragma unroll
        for (int j = 0; j < 8; j++) { p[j][0] = p[j][1] = p[j][2] = p[j][3] = 0.f; }
#pragma unroll
        for (int ks = 0; ks < 8; ks++) {
            const int kp = ks * 8 + 2 * q4;
            uint2 qlo = *(const uint2*)&Qw[rq * QST + kp];
            uint2 qhi = *(const uint2*)&Qw[(rq + 8) * QST + kp];
#pragma unroll
            for (int j = 0; j < 8; j++) {
                int n = (8 + j) * 8 + rq;
                uint2 kb = *(const uint2*)&Ks[n * KST + kp];
                mma8(p[j], qlo.x, qhi.x, qlo.y, qhi.y, kb.x, kb.y);
            }
        }
#pragma unroll
        for (int j = 0; j < 8; j++) {
            int c0 = kt * 128 + (8 + j) * 8 + 2 * q4;
            float e0 = (!diag || c0     <= rbase    ) ? __expf(p[j][0]) : 0.f;
            float e1 = (!diag || c0 + 1 <= rbase    ) ? __expf(p[j][1]) : 0.f;
            float e2 = (!diag || c0     <= rbase + 8) ? __expf(p[j][2]) : 0.f;
            float e3 = (!diag || c0 + 1 <= rbase + 8) ? __expf(p[j][3]) : 0.f;
            p[j][0] = e0; p[j][1] = e1; p[j][2] = e2; p[j][3] = e3;
            l0 += e0 + e1; l1 += e2 + e3;
        }

        __syncthreads();
        if (kt < qt) { loadK(kt + 1); cp_commit(); }

        // PV half 1
#pragma unroll
        for (int t = 0; t < 8; t++) {
            unsigned a0 = f2tf32(p[t][0]);
            unsigned a1 = f2tf32(p[t][2]);
            unsigned a2 = f2tf32(p[t][1]);
            unsigned a3 = f2tf32(p[t][3]);
            int krp = (8 + t) * 8 + 2 * q4;
#pragma unroll
            for (int j = 0; j < 8; j++) {
                int n = j * 8 + rq;
                uint2 vb = *(const uint2*)&Vs[n * VST + krp];
                mma8(cacc[j], a0, a1, a2, a3, vb.x, vb.y);
            }
        }

        __syncthreads();
        if (kt < qt) { loadV(kt + 1); cp_commit(); }
    }

    l0 += __shfl_xor_sync(0xffffffffu, l0, 1);
    l0 += __shfl_xor_sync(0xffffffffu, l0, 2);
    l1 += __shfl_xor_sync(0xffffffffu, l1, 1);
    l1 += __shfl_xor_sync(0xffffffffu, l1, 2);
    float inv0 = 1.0f / l0, inv1 = 1.0f / l1;

    // row inverses for pass B
    if (q4 == 0) {
        linv[(long long)z * Sq + rbase]     = inv0;
        linv[(long long)z * Sq + rbase + 8] = inv1;
    }

    // ctx epilogue -> tf32 bits, d-permuted
    {
        int b_ = z >> 4, h_ = z & 15;
        long long base0 = ((long long)b_ * Sq + rbase) * DM + h_ * 64;
        long long base1 = base0 + 8LL * DM;
        int r0 = 2 * q4;
        int p0 = perm8(r0), p1 = perm8(r0 + 1);
#pragma unroll
        for (int j = 0; j < 8; j++) {
            int g = j * 8;
            ctx[base0 + g + p0] = f2tf32(cacc[j][0] * inv0);
            ctx[base0 + g + p1] = f2tf32(cacc[j][1] * inv0);
            ctx[base1 + g + p0] = f2tf32(cacc[j][2] * inv1);
            ctx[base1 + g + p1] = f2tf32(cacc[j][3] * inv1);
        }
    }
}

// ---------------------------------------------------------------------------
// Fused tail, role-INTERLEAVED: blockIdx%3==0 -> out-proj GEMM (256 blocks);
// else -> attn pass B (512 blocks, long-qt first). Each scheduling wave mixes
// tensor-bound GEMM with DRAM-bound pass B. attn writes use streaming stores
// (__stcs) — write-once data, keep it out of L2.
// ---------------------------------------------------------------------------
struct FuseP {
    const unsigned *ctx, *wo; const float* bo; float* Y;   // out-proj
    const unsigned *qh, *kh; float* attn; const float* linv;
    int write_attn;
};

#define FB_SMEM_BYTES (4 * BUF_WORDS * 4)   // 80 KB covers both roles

__global__ __launch_bounds__(256, 2)
void fused_bo(FuseP f)
{
    extern __shared__ unsigned smu[];
    const int tid = threadIdx.x, lane = tid & 31, warp = tid >> 5;

    const int bx = blockIdx.x;
    if (bx % 3 == 0) {
        // ================= out-proj GEMM (A tf32 d-perm, W tf32 k-perm) =====
        constexpr int AS_ = 40;
        int obx = bx / 3;                       // 0..255
        const int n0 = (obx & 7) * 128;
        const int m0 = (obx >> 3) * 128;
        const int wm = warp & 1, wn = warp >> 1;

        unsigned* Abuf[2] = { smu,                 smu + BUF_WORDS     };
        unsigned* Bbuf[2] = { smu + 2 * BUF_WORDS, smu + 3 * BUF_WORDS };

        auto loadA = [&](unsigned* As_, int k0) {
            int r0 = tid >> 3, c = (tid & 7) * 4;
#pragma unroll
            for (int it = 0; it < 4; it++) {
                int r = r0 + it * 32;
                cpa16(&As_[r * AS_ + c], &f.ctx[(long long)(m0 + r) * DM + k0 + c]);
            }
        };
        auto loadB = [&](unsigned* Bs_, int k0) {
            int r0 = tid >> 3, c = (tid & 7) * 4;
#pragma unroll
            for (int it = 0; it < 4; it++) {
                int r = r0 + it * 32;
                cpa16(&Bs_[r * AS_ + c], &f.wo[(long long)(n0 + r) * DM + k0 + c]);
            }
        };

        float acc[4][4][4] = {};
        loadA(Abuf[0], 0); loadB(Bbuf[0], 0); cp_commit();
        int st = 0;
        for (int k0 = 0; k0 < DM; k0 += 32) {
            if (k0 + 32 < DM) { loadA(Abuf[st ^ 1], k0 + 32); loadB(Bbuf[st ^ 1], k0 + 32); }
            cp_commit();
            cp_wait1();
            __syncthreads();

            const unsigned* As_ = Abuf[st];
            const unsigned* Bs_ = Bbuf[st];
#pragma unroll
            for (int kk = 0; kk < 32; kk += 8) {
                const int kp = kk + 2 * (lane & 3);
                unsigned a[4][4];
#pragma unroll
                for (int i = 0; i < 4; i++) {
                    int mr = wm * 64 + i * 16 + (lane >> 2);
                    uint2 lo = *(const uint2*)&As_[mr * AS_ + kp];
                    uint2 hi = *(const uint2*)&As_[(mr + 8) * AS_ + kp];
                    a[i][0] = lo.x; a[i][1] = hi.x; a[i][2] = lo.y; a[i][3] = hi.y;
                }
                unsigned b[4][2];
#pragma unroll
                for (int j = 0; j < 4; j++) {
                    int nr = wn * 32 + j * 8 + (lane >> 2);
                    uint2 bb = *(const uint2*)&Bs_[nr * AS_ + kp];
                    b[j][0] = bb.x; b[j][1] = bb.y;
                }
#pragma unroll
                for (int i = 0; i < 4; i++)
#pragma unroll
                    for (int j = 0; j < 4; j++)
                        mma8(acc[i][j], a[i][0], a[i][1], a[i][2], a[i][3], b[j][0], b[j][1]);
            }
            __syncthreads();
            st ^= 1;
        }

#pragma unroll
        for (int i = 0; i < 4; i++)
#pragma unroll
            for (int j = 0; j < 4; j++)
#pragma unroll
                for (int h = 0; h < 2; h++) {
                    int m = m0 + wm * 64 + i * 16 + (lane >> 2) + h * 8;
                    int n = n0 + wn * 32 + j * 8 + (lane & 3) * 2;
                    float v0 = acc[i][j][h * 2]     + f.bo[n];
                    float v1 = acc[i][j][h * 2 + 1] + f.bo[n + 1];
                    *(float2*)&f.Y[(long long)m * DM + n] = make_float2(v0, v1);
                }
        return;
    }

    // ================= attn pass B =========================================
    if (!f.write_attn) return;
    const int pb = (bx / 3) * 2 + (bx % 3) - 1;       // 0..511
    const int z  = pb & 31;
    const int qt = 15 - (pb >> 5);                    // long blocks first

    unsigned* Qs = smu;
    unsigned* Ks = smu + FK_OFF;

    const unsigned* Qg = f.qh + ((long long)z * Sq + qt * 128) * DHq;
    const unsigned* Kg = f.kh + (long long)z * Sq * DHq;
    float* A = f.attn + (long long)z * Sq * Sq;

    for (int i = tid; i < 128 * 16; i += 256) {
        int r = i >> 4, c4 = (i & 15) * 4;
        *(uint4*)&Qs[r * QST + c4] = *(const uint4*)&Qg[r * 64 + c4];
    }

    auto loadK = [&](int kt) {
        for (int i = tid; i < 128 * 16; i += 256) {
            int r = i >> 4, c4 = (i & 15) * 4;
            cpa16(&Ks[r * KST + c4], &Kg[((long long)kt * 128 + r) * 64 + c4]);
        }
    };

    const unsigned* Qw = &Qs[(warp * 16) * QST];
    const int rq = lane >> 2;
    const int q4 = lane & 3;
    const int rbase = qt * 128 + warp * 16 + rq;

    float inv0 = f.linv[(long long)z * Sq + rbase];
    float inv1 = f.linv[(long long)z * Sq + rbase + 8];

    float p[8][4];

    loadK(0); cp_commit();
    for (int kt = 0; kt <= qt; kt++) {
        cp_wait0();
        __syncthreads();

        bool diag = (kt == qt);
        long long row0 = (long long)rbase * Sq;
        long long row1 = (long long)(rbase + 8) * Sq;

        // S half 0 + write (streaming stores)
#pragma unroll
        for (int j = 0; j < 8; j++) { p[j][0] = p[j][1] = p[j][2] = p[j][3] = 0.f; }
#pragma unroll
        for (int ks = 0; ks < 8; ks++) {
            const int kp = ks * 8 + 2 * q4;
            uint2 qlo = *(const uint2*)&Qw[rq * QST + kp];
            uint2 qhi = *(const uint2*)&Qw[(rq + 8) * QST + kp];
#pragma unroll
            for (int j = 0; j < 8; j++) {
                int n = j * 8 + rq;
                uint2 kb = *(const uint2*)&Ks[n * KST + kp];
                mma8(p[j], qlo.x, qhi.x, qlo.y, qhi.y, kb.x, kb.y);
            }
        }
#pragma unroll
        for (int j = 0; j < 8; j++) {
            int c0 = kt * 128 + j * 8 + 2 * q4;
            float e0 = (!diag || c0     <= rbase    ) ? __expf(p[j][0]) * inv0 : 0.f;
            float e1 = (!diag || c0 + 1 <= rbase    ) ? __expf(p[j][1]) * inv0 : 0.f;
            float e2 = (!diag || c0     <= rbase + 8) ? __expf(p[j][2]) * inv1 : 0.f;
            float e3 = (!diag || c0 + 1 <= rbase + 8) ? __expf(p[j][3]) * inv1 : 0.f;
            __stcs((float2*)&A[row0 + c0], make_float2(e0, e1));
            __stcs((float2*)&A[row1 + c0], make_float2(e2, e3));
        }

        // S half 1 mma, prefetch K overlapped with epilogue
#pragma unroll
        for (int j = 0; j < 8; j++) { p[j][0] = p[j][1] = p[j][2] = p[j][3] = 0.f; }
#pragma unroll
        for (int ks = 0; ks < 8; ks++) {
            const int kp = ks * 8 + 2 * q4;
            uint2 qlo = *(const uint2*)&Qw[rq * QST + kp];
            uint2 qhi = *(const uint2*)&Qw[(rq + 8) * QST + kp];
#pragma unroll
            for (int j = 0; j < 8; j++) {
                int n = (8 + j) * 8 + rq;
                uint2 kb = *(const uint2*)&Ks[n * KST + kp];
                mma8(p[j], qlo.x, qhi.x, qlo.y, qhi.y, kb.x, kb.y);
            }
        }
        __syncthreads();
        if (kt < qt) { loadK(kt + 1); cp_commit(); }
#pragma unroll
        for (int j = 0; j < 8; j++) {
            int c0 = kt * 128 + (8 + j) * 8 + 2 * q4;
            float e0 = (!diag || c0     <= rbase    ) ? __expf(p[j][0]) * inv0 : 0.f;
            float e1 = (!diag || c0 + 1 <= rbase    ) ? __expf(p[j][1]) * inv0 : 0.f;
            float e2 = (!diag || c0     <= rbase + 8) ? __expf(p[j][2]) * inv1 : 0.f;
            float e3 = (!diag || c0 + 1 <= rbase + 8) ? __expf(p[j][3]) * inv1 : 0.f;
            __stcs((float2*)&A[row0 + c0], make_float2(e0, e1));
            __stcs((float2*)&A[row1 + c0], make_float2(e2, e3));
        }
    }

    // zero-fill the strictly-causal-upper region (row-per-warp, streaming)
    int cEnd = (qt + 1) * 128;
    if (cEnd < Sq) {
        float4 z4 = make_float4(0.f, 0.f, 0.f, 0.f);
        for (int r = warp; r < 128; r += 8) {
            float* row = &A[(long long)(qt * 128 + r) * Sq];
            for (int c = cEnd + lane * 4; c < Sq; c += 128)
                __stcs((float4*)&row[c], z4);
        }
    }
}

// ---------------------------------------------------------------------------
// kernel_launch
// ---------------------------------------------------------------------------
extern "C" void kernel_launch(void* const* d_in, const int* in_sizes, int n_in,
                              void* d_out, int out_size)
{
    const float* q  = (const float*)d_in[0];
    const float* k  = (const float*)d_in[1];
    const float* v  = (const float*)d_in[2];
    // d_in[3] = causal tril mask (handled analytically)
    const float* wq = (const float*)d_in[4];
    const float* bq = (const float*)d_in[5];
    const float* wk = (const float*)d_in[6];
    const float* bk = (const float*)d_in[7];
    const float* wv = (const float*)d_in[8];
    const float* bv = (const float*)d_in[9];
    const float* wo = (const float*)d_in[10];
    const float* bo = (const float*)d_in[11];
    float* out = (float*)d_out;

    unsigned *qh, *kh, *vh, *ctx, *pwq, *pwk, *pwv, *pwo;
    float* linv;
    cudaGetSymbolAddress((void**)&qh,   g_qh);
    cudaGetSymbolAddress((void**)&kh,   g_kh);
    cudaGetSymbolAddress((void**)&vh,   g_vh);
    cudaGetSymbolAddress((void**)&ctx,  g_ctx);
    cudaGetSymbolAddress((void**)&linv, g_linv);
    cudaGetSymbolAddress((void**)&pwq,  g_wq);
    cudaGetSymbolAddress((void**)&pwk,  g_wk);
    cudaGetSymbolAddress((void**)&pwv,  g_wv);
    cudaGetSymbolAddress((void**)&pwo,  g_wo);

    const long long OUT_E  = (long long)Bq * Sq * DM;
    const long long ATTN_E = (long long)Bq * Hq * Sq * Sq;
    int write_attn = ((long long)out_size >= OUT_E + ATTN_E) ? 1 : 0;
    float* attn = out + OUT_E;

    static int attr_done = 0;
    if (!attr_done) {
        cudaFuncSetAttribute(gemm_qkv,
                             cudaFuncAttributeMaxDynamicSharedMemorySize, G_SMEM_BYTES);
        cudaFuncSetAttribute(attn_flash_a,
                             cudaFuncAttributeMaxDynamicSharedMemorySize, F_SMEM_BYTES);
        cudaFuncSetAttribute(fused_bo,
                             cudaFuncAttributeMaxDynamicSharedMemorySize, FB_SMEM_BYTES);
        attr_done = 1;
    }

    // 0: prep — WEIGHTS only -> tf32 bits, K-permuted
    PrepP pp;
    pp.in[0] = wq; pp.out[0] = pwq;
    pp.in[1] = wk; pp.out[1] = pwk;
    pp.in[2] = wv; pp.out[2] = pwv;
    pp.in[3] = wo; pp.out[3] = pwo;
    prep_cvt<<<dim3((DM * DM) / (256 * 4), 4), 256>>>(pp);

    // 1: fused QKV projections
    GemmP pq = {};
    pq.X  = (const unsigned*)q; pq.W  = pwq; pq.b0_ = bq; pq.Y  = qh;
    pq.X1 = (const unsigned*)k; pq.W1 = pwk; pq.b1_ = bk; pq.Y1 = kh;
    pq.X2 = (const unsigned*)v; pq.W2 = pwv; pq.b2_ = bv; pq.Y2 = vh;
    pq.K = DM;
    pq.ps[0] = 0.125f; pq.ps[1] = 1.f; pq.ps[2] = 1.f;
    pq.nperm[0] = 1; pq.nperm[1] = 1; pq.nperm[2] = 2;
    gemm_qkv<<<dim3(DM / 128, (Bq * Sq) / 128, 3), 256, G_SMEM_BYTES>>>(pq);

    // 2: flash pass A (ctx + row inverses)
    attn_flash_a<<<dim3(Sq / 128, Bq * Hq, 1), 256, F_SMEM_BYTES>>>(
        qh, kh, vh, ctx, linv);

    // 3: fused tail — roles interleaved blockIdx%3 (1/3 GEMM + 2/3 pass B)
    FuseP f = {};
    f.ctx = ctx; f.wo = pwo; f.bo = bo; f.Y = out;
    f.qh = qh; f.kh = kh; f.attn = attn; f.linv = linv;
    f.write_attn = write_attn;
    fused_bo<<<768, 256, FB_SMEM_BYTES>>>(f);
}